// round 15
// baseline (speedup 1.0000x reference)
#include <cuda_runtime.h>
#include <cstddef>
#include <cstdint>

// Problem constants
#define BATCH 2
#define SEQ   2048
#define DMODEL 1024
#define NHEADS 16
#define DHEAD 64
#define MROWS (BATCH*SEQ)        // 4096

// ---------------- scratch (no allocation allowed) ----------------
// g_q: [B,H,S,Dh] Dh 8-group interleaved (tf32)
// g_k: [B,H,S,Dh] Dh 8-group interleaved AND S-rows 8-group interleaved (tf32)
// g_v: [B,H,Dh,S] S 8-group interleaved (tf32)
// g_ao: [M, DMODEL] k-columns 8-group interleaved, tf32 (O-GEMM A-side)
__device__ float g_q[BATCH*NHEADS*SEQ*DHEAD];
__device__ float g_k[BATCH*NHEADS*SEQ*DHEAD];
__device__ float g_v[BATCH*NHEADS*SEQ*DHEAD];
__device__ float g_ao[MROWS*DMODEL];
// k-permuted + tf32-rounded copies of inputs
__device__ float g_rx[3][MROWS*DMODEL];         // query/key_/value
__device__ float g_rw[4][DMODEL*DMODEL];        // Wq/Wk/Wv/Wo

// ---------------- helpers ----------------
__device__ __forceinline__ float cvt_tf32f(float x) {
    unsigned u;
    asm("cvt.rna.tf32.f32 %0, %1;" : "=r"(u) : "f"(x));
    return __uint_as_float(u);
}

__device__ __forceinline__ float ex2f(float x) {
    float y;
    asm("ex2.approx.ftz.f32 %0, %1;" : "=f"(y) : "f"(x));
    return y;
}

// interleave within 8-group: old offset o -> new position
__device__ __forceinline__ int perm8(int o) {
    return (o < 4) ? (2 * o) : (2 * o - 7);
}

__device__ __forceinline__ void mma_tf32(float* c, const unsigned* a, const unsigned* b) {
    asm volatile(
        "mma.sync.aligned.m16n8k8.row.col.f32.tf32.tf32.f32 "
        "{%0,%1,%2,%3}, {%4,%5,%6,%7}, {%8,%9}, {%0,%1,%2,%3};"
        : "+f"(c[0]), "+f"(c[1]), "+f"(c[2]), "+f"(c[3])
        : "r"(a[0]), "r"(a[1]), "r"(a[2]), "r"(a[3]),
          "r"(b[0]), "r"(b[1]));
}

__device__ __forceinline__ uint32_t smem_u32(const void* p) {
    uint32_t a;
    asm("{ .reg .u64 t; cvta.to.shared.u64 t, %1; cvt.u32.u64 %0, t; }"
        : "=r"(a) : "l"(p));
    return a;
}

__device__ __forceinline__ void cpa16(uint32_t dst, const void* src) {
    asm volatile("cp.async.cg.shared.global [%0], [%1], 16;"
                 :: "r"(dst), "l"(src) : "memory");
}
#define CPA_COMMIT() asm volatile("cp.async.commit_group;" ::: "memory")
#define CPA_WAIT1()  asm volatile("cp.async.wait_group 1;" ::: "memory")
#define CPA_WAIT0()  asm volatile("cp.async.wait_group 0;" ::: "memory")

// ---------------- pre-pass: k-column 8-group interleave + tf32 round -------
// new layout per 8-group: [old0, old4, old1, old5, old2, old6, old3, old7]
struct PArgs {
    const float* in[7];
    float* out[7];
    int n8[7];
};

__global__ __launch_bounds__(256) void permute_round(PArgs pa)
{
    const int z = blockIdx.y;
    const int i = blockIdx.x * 256 + threadIdx.x;
    if (i >= pa.n8[z]) return;
    const float4* src = (const float4*)pa.in[z] + 2 * (size_t)i;
    float4 lo = src[0], hi = src[1];
    float4 o0, o1;
    o0.x = cvt_tf32f(lo.x);  // new0 = old0
    o0.y = cvt_tf32f(hi.x);  // new1 = old4
    o0.z = cvt_tf32f(lo.y);  // new2 = old1
    o0.w = cvt_tf32f(hi.y);  // new3 = old5
    o1.x = cvt_tf32f(lo.z);  // new4 = old2
    o1.y = cvt_tf32f(hi.z);  // new5 = old6
    o1.z = cvt_tf32f(lo.w);  // new6 = old3
    o1.w = cvt_tf32f(hi.w);  // new7 = old7
    float4* dst = (float4*)pa.out[z] + 2 * (size_t)i;
    dst[0] = o0; dst[1] = o1;
}

// ---------------- GEMM (tf32 mma, LDS.64 frags, 256 thr / 32x64 warp tiles)
// Inputs pre-permuted (k 8-group interleave) + pre-rounded.
// CTA tile 128x128x32, 256 threads = 8 warps (4m x 2n), warp tile 32x64.
// 2-stage cp.async, 1 sync/iter. ~100 regs/thread -> 2 CTAs/SM = 16 warps.
// mode 0: plain [M,N] fp32 (O projection)
// mode 1: [B,H,S,Dh], Dh 8-group interleaved, tf32 (Q)
// mode 2: [B,H,Dh,S], S 8-group interleaved, tf32 (V)
// mode 3: like mode 1 plus S-row 8-group interleave (K)
#define GP 40
#define G_STAGE 10240
#define G_BOFF  5120
#define G_SMEM_FLOATS (2 * G_STAGE)     // 81920 bytes

struct GArgs {
    const float* X[3];
    const float* W[3];
    const float* bias[3];
    float*       Y[3];
    int mode[3];
};

__global__ __launch_bounds__(256) void gemm_tf32(GArgs ga)
{
    extern __shared__ float sg[];
    const uint32_t smb = smem_u32(sg);

    const int z = blockIdx.z;
    const float* __restrict__ X    = ga.X[z];
    const float* __restrict__ W    = ga.W[z];
    const float* __restrict__ bias = ga.bias[z];
    float* __restrict__       Y    = ga.Y[z];
    const int mode = ga.mode[z];

    const int t    = threadIdx.x;
    const int lane = t & 31;
    const int wid  = t >> 5;           // 0..7
    const int gid  = lane >> 2;
    const int tg   = lane & 3;

    const int bm = blockIdx.y * 128;
    const int bn = blockIdx.x * 128;
    const int m_base = (wid >> 1) * 32;   // 4 m-groups of 32 rows
    const int n_base = (wid & 1) * 64;    // 2 n-groups of 64 cols

    float acc[2][8][4];
    #pragma unroll
    for (int mt = 0; mt < 2; mt++)
        #pragma unroll
        for (int nt = 0; nt < 8; nt++)
            #pragma unroll
            for (int i = 0; i < 4; i++) acc[mt][nt][i] = 0.f;

    // prologue: prefetch chunk 0 into stage 0 (256 threads, 4 iters)
    {
        const float* xs = X + (size_t)bm * DMODEL;
        const float* ws = W + (size_t)bn * DMODEL;
        #pragma unroll
        for (int l = 0; l < 4; l++) {
            int id = t + 256 * l;            // 0..1023
            int r  = id >> 3, q = id & 7;
            cpa16(smb + (uint32_t)(r * GP + q * 4) * 4,
                  xs + (size_t)r * DMODEL + q * 4);
            cpa16(smb + (uint32_t)(G_BOFF + r * GP + q * 4) * 4,
                  ws + (size_t)r * DMODEL + q * 4);
        }
        CPA_COMMIT();
    }

    for (int c = 0; c < 32; c++) {
        CPA_WAIT0();        // chunk c resident
        __syncthreads();

        if (c + 1 < 32) {
            const int naof = ((c + 1) & 1) * G_STAGE;
            const int k0   = (c + 1) * 32;
            const float* xs = X + (size_t)bm * DMODEL + k0;
            const float* ws = W + (size_t)bn * DMODEL + k0;
            #pragma unroll
            for (int l = 0; l < 4; l++) {
                int id = t + 256 * l;
                int r  = id >> 3, q = id & 7;
                cpa16(smb + (uint32_t)(naof + r * GP + q * 4) * 4,
                      xs + (size_t)r * DMODEL + q * 4);
                cpa16(smb + (uint32_t)(naof + G_BOFF + r * GP + q * 4) * 4,
                      ws + (size_t)r * DMODEL + q * 4);
            }
            CPA_COMMIT();
        }

        const float* As = sg + (c & 1) * G_STAGE;
        const float* Bs = As + G_BOFF;
        #pragma unroll
        for (int ks = 0; ks < 4; ks++) {
            const int kb = ks * 8;
            unsigned afr[2][4];
            #pragma unroll
            for (int mt = 0; mt < 2; mt++) {
                int m = m_base + mt * 16;
                float2 a0 = *(const float2*)&As[(m + gid    ) * GP + kb + 2 * tg];
                float2 a1 = *(const float2*)&As[(m + gid + 8) * GP + kb + 2 * tg];
                afr[mt][0] = __float_as_uint(a0.x);
                afr[mt][1] = __float_as_uint(a1.x);
                afr[mt][2] = __float_as_uint(a0.y);
                afr[mt][3] = __float_as_uint(a1.y);
            }
            unsigned bfr[8][2];
            #pragma unroll
            for (int nt = 0; nt < 8; nt++) {
                int n = n_base + nt * 8;
                float2 bb = *(const float2*)&Bs[(n + gid) * GP + kb + 2 * tg];
                bfr[nt][0] = __float_as_uint(bb.x);
                bfr[nt][1] = __float_as_uint(bb.y);
            }
            #pragma unroll
            for (int mt = 0; mt < 2; mt++)
                #pragma unroll
                for (int nt = 0; nt < 8; nt++)
                    mma_tf32(acc[mt][nt], afr[mt], bfr[nt]);
        }
    }

    // epilogue
    #pragma unroll
    for (int nt = 0; nt < 8; nt++) {
        int c0 = bn + n_base + nt * 8 + tg * 2;
        float b0 = bias[c0], b1 = bias[c0 + 1];
        #pragma unroll
        for (int mt = 0; mt < 2; mt++) {
            int r0 = bm + m_base + mt * 16 + gid;
            #pragma unroll
            for (int half = 0; half < 2; half++) {
                int m = r0 + half * 8;
                float v0 = acc[mt][nt][half * 2 + 0] + b0;
                float v1 = acc[mt][nt][half * 2 + 1] + b1;
                if (mode == 0) {
                    Y[(size_t)m * DMODEL + c0]     = v0;
                    Y[(size_t)m * DMODEL + c0 + 1] = v1;
                } else if (mode == 1 || mode == 3) {
                    int b_ = m >> 11;
                    int s  = m & (SEQ - 1);
                    if (mode == 3) s = (s & ~7) + perm8(s & 7);   // K: row perm
                    int h  = c0 >> 6;
                    int dh = c0 & (DHEAD - 1);
                    int g8 = dh & ~7, o = dh & 7;
                    size_t base = (((size_t)(b_ * NHEADS + h)) * SEQ + s) * DHEAD + g8;
                    Y[base + perm8(o)]     = cvt_tf32f(v0);
                    Y[base + perm8(o + 1)] = cvt_tf32f(v1);
                } else {
                    int b_ = m >> 11;
                    int s  = m & (SEQ - 1);
                    int h  = c0 >> 6;
                    int dh = c0 & (DHEAD - 1);
                    int sp = (s & ~7) + perm8(s & 7);
                    size_t base = (((size_t)(b_ * NHEADS + h)) * DHEAD + dh) * SEQ + sp;
                    Y[base]       = cvt_tf32f(v0);
                    Y[base + SEQ] = cvt_tf32f(v1);
                }
            }
        }
    }
}

// ---------------- attention: register flash, shuffle-free PV (R13) ---------
// Q: dh-interleaved. K: dh-interleaved + s-row-interleaved (QK c-frag holds
// kv columns {tg, tg+4} -> direct PV a-frag reuse). V: [B,H,Dh,S] s-interleaved.
#define KP 72
#define VP 72
#define A_STAGE 9216
#define A_SMEM_FLOATS (3 * A_STAGE)     // 110592 bytes

#define LOG2E 1.44269504088896340736f

__global__ __launch_bounds__(256) void attn_kernel(
    const float* __restrict__ Q, const float* __restrict__ K,
    const float* __restrict__ V, float* __restrict__ O)
{
    extern __shared__ float sm[];
    const uint32_t smb = smem_u32(sm);

    const int t    = threadIdx.x;
    const int lane = t & 31;
    const int wid  = t >> 5;
    const int gid  = lane >> 2;
    const int tg   = lane & 3;

    const int b  = blockIdx.z, h = blockIdx.y;
    const int q0 = blockIdx.x << 7;
    const size_t head_base = ((size_t)(b * NHEADS + h)) * SEQ * DHEAD;

    // ---- stage Q (scaled 0.125*log2e, tf32) into smem [128][72] ----
    {
        float (*Qs)[KP] = (float (*)[KP])sm;
        const float qs = 0.125f * LOG2E;
        #pragma unroll
        for (int l = 0; l < 8; l++) {
            int id = t + 256 * l;
            int r  = id >> 4;
            int d4 = (id & 15) << 2;
            float4 v = *(const float4*)&Q[head_base + (size_t)(q0 + r) * DHEAD + d4];
            Qs[r][d4+0] = cvt_tf32f(v.x * qs);
            Qs[r][d4+1] = cvt_tf32f(v.y * qs);
            Qs[r][d4+2] = cvt_tf32f(v.z * qs);
            Qs[r][d4+3] = cvt_tf32f(v.w * qs);
        }
    }
    __syncthreads();

    unsigned qf[8][4];
    {
        float (*Qs)[KP] = (float (*)[KP])sm;
        const int wrow = wid * 16;
        #pragma unroll
        for (int ks = 0; ks < 8; ks++) {
            const int kb = ks * 8;
            float2 qa = *(const float2*)&Qs[wrow + gid    ][kb + 2 * tg];
            float2 qb = *(const float2*)&Qs[wrow + gid + 8][kb + 2 * tg];
            qf[ks][0] = __float_as_uint(qa.x);
            qf[ks][1] = __float_as_uint(qb.x);
            qf[ks][2] = __float_as_uint(qa.y);
            qf[ks][3] = __float_as_uint(qb.y);
        }
    }
    __syncthreads();

    // ---- prologue: prefetch KV tiles 0,1 ----
    #pragma unroll
    for (int p = 0; p < 2; p++) {
        const int koff = p * A_STAGE;
        const int voff = p * A_STAGE + 4608;
        #pragma unroll
        for (int l = 0; l < 4; l++) {
            int id = t + 256 * l;
            int r  = id >> 4;
            int c4 = (id & 15) << 2;
            cpa16(smb + (uint32_t)(koff + r * KP + c4) * 4,
                  K + head_base + (size_t)(p * 64 + r) * DHEAD + c4);
            cpa16(smb + (uint32_t)(voff + r * VP + c4) * 4,
                  V + head_base + (size_t)r * SEQ + p * 64 + c4);
        }
        CPA_COMMIT();
    }

    float oacc[8][4];
    #pragma unroll
    for (int nt = 0; nt < 8; nt++)
        #pragma unroll
        for (int i = 0; i < 4; i++) oacc[nt][i] = 0.f;
    float m0 = -1e30f, m1 = -1e30f, l0 = 0.f, l1 = 0.f;

    const int NIT = SEQ / 64;   // 32
    for (int it = 0; it < NIT; it++) {
        if (it + 1 < NIT) { CPA_WAIT1(); } else { CPA_WAIT0(); }
        __syncthreads();

        if (it + 2 < NIT) {
            const int ns = (it + 2) % 3;
            const int nk = ns * A_STAGE;
            const int nv = ns * A_STAGE + 4608;
            #pragma unroll
            for (int l = 0; l < 4; l++) {
                int id = t + 256 * l;
                int r  = id >> 4;
                int c4 = (id & 15) << 2;
                cpa16(smb + (uint32_t)(nk + r * KP + c4) * 4,
                      K + head_base + (size_t)((it + 2) * 64 + r) * DHEAD + c4);
                cpa16(smb + (uint32_t)(nv + r * VP + c4) * 4,
                      V + head_base + (size_t)r * SEQ + (it + 2) * 64 + c4);
            }
            CPA_COMMIT();
        }

        const int stage = it % 3;
        const float* Ks = sm + stage * A_STAGE;
        const float* Vs = sm + stage * A_STAGE + 4608;

        // ---- S2 = (Q*0.125*log2e) K^T (K s-rows permuted: c-frag = kv {tg,tg+4}) ----
        float sacc[8][4];
        #pragma unroll
        for (int nt = 0; nt < 8; nt++)
            #pragma unroll
            for (int i = 0; i < 4; i++) sacc[nt][i] = 0.f;

        #pragma unroll
        for (int ks = 0; ks < 8; ks++) {
            const int kb = ks * 8;
            unsigned bfr[8][2];
            #pragma unroll
            for (int nt = 0; nt < 8; nt++) {
                float2 kk = *(const float2*)&Ks[(nt * 8 + gid) * KP + kb + 2 * tg];
                bfr[nt][0] = __float_as_uint(kk.x);
                bfr[nt][1] = __float_as_uint(kk.y);
            }
            #pragma unroll
            for (int nt = 0; nt < 8; nt++)
                mma_tf32(sacc[nt], qf[ks], bfr[nt]);
        }

        // ---- online softmax, base-2, single-op EX2 ----
        float mx0 = -1e30f, mx1 = -1e30f;
        #pragma unroll
        for (int nt = 0; nt < 8; nt++) {
            mx0 = fmaxf(mx0, fmaxf(sacc[nt][0], sacc[nt][1]));
            mx1 = fmaxf(mx1, fmaxf(sacc[nt][2], sacc[nt][3]));
        }
        mx0 = fmaxf(mx0, __shfl_xor_sync(0xffffffffu, mx0, 1));
        mx0 = fmaxf(mx0, __shfl_xor_sync(0xffffffffu, mx0, 2));
        mx1 = fmaxf(mx1, __shfl_xor_sync(0xffffffffu, mx1, 1));
        mx1 = fmaxf(mx1, __shfl_xor_sync(0xffffffffu, mx1, 2));

        float m0n = fmaxf(m0, mx0), m1n = fmaxf(m1, mx1);
        float sc0 = ex2f(m0 - m0n), sc1 = ex2f(m1 - m1n);
        m0 = m0n; m1 = m1n;

        float s0 = 0.f, s1 = 0.f;
        #pragma unroll
        for (int nt = 0; nt < 8; nt++) {
            sacc[nt][0] = ex2f(sacc[nt][0] - m0); s0 += sacc[nt][0];
            sacc[nt][1] = ex2f(sacc[nt][1] - m0); s0 += sacc[nt][1];
            sacc[nt][2] = ex2f(sacc[nt][2] - m1); s1 += sacc[nt][2];
            sacc[nt][3] = ex2f(sacc[nt][3] - m1); s1 += sacc[nt][3];
        }
        s0 += __shfl_xor_sync(0xffffffffu, s0, 1);
        s0 += __shfl_xor_sync(0xffffffffu, s0, 2);
        s1 += __shfl_xor_sync(0xffffffffu, s1, 1);
        s1 += __shfl_xor_sync(0xffffffffu, s1, 2);
        l0 = l0 * sc0 + s0;
        l1 = l1 * sc1 + s1;

        #pragma unroll
        for (int nt = 0; nt < 8; nt++) {
            oacc[nt][0] *= sc0; oacc[nt][1] *= sc0;
            oacc[nt][2] *= sc1; oacc[nt][3] *= sc1;
        }

        // ---- PV: a-frags are direct register renames of sacc ----
        #pragma unroll
        for (int ks = 0; ks < 8; ks++) {
            unsigned a[4];
            a[0] = __float_as_uint(sacc[ks][0]);
            a[1] = __float_as_uint(sacc[ks][2]);
            a[2] = __float_as_uint(sacc[ks][1]);
            a[3] = __float_as_uint(sacc[ks][3]);

            const int kb = ks * 8;
            #pragma unroll
            for (int nt = 0; nt < 8; nt++) {
                float2 vv = *(const float2*)&Vs[(nt * 8 + gid) * VP + kb + 2 * tg];
                unsigned b2[2];
                b2[0] = __float_as_uint(vv.x);
                b2[1] = __float_as_uint(vv.y);
                mma_tf32(oacc[nt], a, b2);
            }
        }
    }

    // ---- epilogue: normalize, write k-interleaved rounded [B,S,D] ----
    {
        float il0 = 1.0f / l0, il1 = 1.0f / l1;
        int r0 = q0 + wid * 16 + gid;
        int r1 = r0 + 8;
        const int o = tg * 2;
        const int p0i = perm8(o), p1i = perm8(o + 1);
        #pragma unroll
        for (int nt = 0; nt < 8; nt++) {
            int cbase = h * DHEAD + nt * 8;
            size_t base0 = ((size_t)(b * SEQ + r0)) * DMODEL + cbase;
            size_t base1 = ((size_t)(b * SEQ + r1)) * DMODEL + cbase;
            O[base0 + p0i] = cvt_tf32f(oacc[nt][0] * il0);
            O[base0 + p1i] = cvt_tf32f(oacc[nt][1] * il0);
            O[base1 + p0i] = cvt_tf32f(oacc[nt][2] * il1);
            O[base1 + p1i] = cvt_tf32f(oacc[nt][3] * il1);
        }
    }
}

extern "C" void kernel_launch(void* const* d_in, const int* in_sizes, int n_in,
                              void* d_out, int out_size)
{
    const float* query = (const float*)d_in[0];
    const float* key_  = (const float*)d_in[1];
    const float* value = (const float*)d_in[2];
    const float* Wq = (const float*)d_in[3];
    const float* bq = (const float*)d_in[4];
    const float* Wk = (const float*)d_in[5];
    const float* bk = (const float*)d_in[6];
    const float* Wv = (const float*)d_in[7];
    const float* bv = (const float*)d_in[8];
    const float* Wo = (const float*)d_in[9];
    const float* bo = (const float*)d_in[10];

    float *qptr, *kptr, *vptr, *aoptr, *rxptr, *rwptr;
    cudaGetSymbolAddress((void**)&qptr,  g_q);
    cudaGetSymbolAddress((void**)&kptr,  g_k);
    cudaGetSymbolAddress((void**)&vptr,  g_v);
    cudaGetSymbolAddress((void**)&aoptr, g_ao);
    cudaGetSymbolAddress((void**)&rxptr, g_rx);
    cudaGetSymbolAddress((void**)&rwptr, g_rw);

    float* rq  = rxptr;
    float* rk  = rxptr + (size_t)MROWS * DMODEL;
    float* rv  = rxptr + 2 * (size_t)MROWS * DMODEL;
    float* rwq = rwptr;
    float* rwk = rwptr + (size_t)DMODEL * DMODEL;
    float* rwv = rwptr + 2 * (size_t)DMODEL * DMODEL;
    float* rwo = rwptr + 3 * (size_t)DMODEL * DMODEL;

    const int gemm_smem = G_SMEM_FLOATS * sizeof(float);   // 81920
    const int attn_smem = A_SMEM_FLOATS * sizeof(float);   // 110592
    cudaFuncSetAttribute(gemm_tf32, cudaFuncAttributeMaxDynamicSharedMemorySize, gemm_smem);
    cudaFuncSetAttribute(attn_kernel, cudaFuncAttributeMaxDynamicSharedMemorySize, attn_smem);

    // one fused pre-pass: k-permute (8-group) + tf32-round all 7 GEMM operands
    PArgs pa;
    pa.in[0] = query; pa.out[0] = rq;  pa.n8[0] = MROWS * DMODEL / 8;
    pa.in[1] = key_;  pa.out[1] = rk;  pa.n8[1] = MROWS * DMODEL / 8;
    pa.in[2] = value; pa.out[2] = rv;  pa.n8[2] = MROWS * DMODEL / 8;
    pa.in[3] = Wq;    pa.out[3] = rwq; pa.n8[3] = DMODEL * DMODEL / 8;
    pa.in[4] = Wk;    pa.out[4] = rwk; pa.n8[4] = DMODEL * DMODEL / 8;
    pa.in[5] = Wv;    pa.out[5] = rwv; pa.n8[5] = DMODEL * DMODEL / 8;
    pa.in[6] = Wo;    pa.out[6] = rwo; pa.n8[6] = DMODEL * DMODEL / 8;
    dim3 pgrid((MROWS * DMODEL / 8 + 255) / 256, 7);
    permute_round<<<pgrid, 256>>>(pa);

    // fused QKV projections (grid.z selects matrix)
    GArgs qkv;
    qkv.X[0] = rq; qkv.W[0] = rwq; qkv.bias[0] = bq; qkv.Y[0] = qptr; qkv.mode[0] = 1;
    qkv.X[1] = rk; qkv.W[1] = rwk; qkv.bias[1] = bk; qkv.Y[1] = kptr; qkv.mode[1] = 3;
    qkv.X[2] = rv; qkv.W[2] = rwv; qkv.bias[2] = bv; qkv.Y[2] = vptr; qkv.mode[2] = 2;
    dim3 qkvgrid(DMODEL / 128, MROWS / 128, 3);   // (8, 32, 3)
    gemm_tf32<<<qkvgrid, 256, gemm_smem>>>(qkv);

    dim3 agrid(SEQ / 128, NHEADS, BATCH);         // (16, 16, 2)
    attn_kernel<<<agrid, 256, attn_smem>>>(qptr, kptr, vptr, aoptr);

    GArgs og;
    og.X[0] = aoptr; og.W[0] = rwo; og.bias[0] = bo; og.Y[0] = (float*)d_out; og.mode[0] = 0;
    og.X[1] = aoptr; og.W[1] = rwo; og.bias[1] = bo; og.Y[1] = (float*)d_out; og.mode[1] = 0;
    og.X[2] = aoptr; og.W[2] = rwo; og.bias[2] = bo; og.Y[2] = (float*)d_out; og.mode[2] = 0;
    dim3 ogrid(DMODEL / 128, MROWS / 128, 1);     // (8, 32, 1)
    gemm_tf32<<<ogrid, 256, gemm_smem>>>(og);
}

// round 16
// speedup vs baseline: 1.0382x; 1.0382x over previous
#include <cuda_runtime.h>
#include <cstddef>
#include <cstdint>

// Problem constants
#define BATCH 2
#define SEQ   2048
#define DMODEL 1024
#define NHEADS 16
#define DHEAD 64
#define MROWS (BATCH*SEQ)        // 4096

#define LOG2E 1.44269504088896340736f
#define QSC  (0.125f * LOG2E)

// ---------------- scratch (no allocation allowed) ----------------
// g_q: [B,H,S,Dh] Dh 8-group interleaved, PRE-SCALED by 0.125*log2e (tf32)
// g_k: [B,H,S,Dh] Dh 8-group interleaved AND S-rows 8-group interleaved (tf32)
// g_v: [B,H,Dh,S] S 8-group interleaved (tf32)
// g_ao: [M, DMODEL] k-columns 8-group interleaved, tf32 (O-GEMM A-side)
__device__ float g_q[BATCH*NHEADS*SEQ*DHEAD];
__device__ float g_k[BATCH*NHEADS*SEQ*DHEAD];
__device__ float g_v[BATCH*NHEADS*SEQ*DHEAD];
__device__ float g_ao[MROWS*DMODEL];
// k-permuted + tf32-rounded copies of inputs
__device__ float g_rx[3][MROWS*DMODEL];         // query/key_/value
__device__ float g_rw[4][DMODEL*DMODEL];        // Wq/Wk/Wv/Wo

// ---------------- helpers ----------------
__device__ __forceinline__ float cvt_tf32f(float x) {
    unsigned u;
    asm("cvt.rna.tf32.f32 %0, %1;" : "=r"(u) : "f"(x));
    return __uint_as_float(u);
}

__device__ __forceinline__ float ex2f(float x) {
    float y;
    asm("ex2.approx.ftz.f32 %0, %1;" : "=f"(y) : "f"(x));
    return y;
}

// interleave within 8-group: old offset o -> new position
__device__ __forceinline__ int perm8(int o) {
    return (o < 4) ? (2 * o) : (2 * o - 7);
}

__device__ __forceinline__ void mma_tf32(float* c, const unsigned* a, const unsigned* b) {
    asm volatile(
        "mma.sync.aligned.m16n8k8.row.col.f32.tf32.tf32.f32 "
        "{%0,%1,%2,%3}, {%4,%5,%6,%7}, {%8,%9}, {%0,%1,%2,%3};"
        : "+f"(c[0]), "+f"(c[1]), "+f"(c[2]), "+f"(c[3])
        : "r"(a[0]), "r"(a[1]), "r"(a[2]), "r"(a[3]),
          "r"(b[0]), "r"(b[1]));
}

__device__ __forceinline__ uint32_t smem_u32(const void* p) {
    uint32_t a;
    asm("{ .reg .u64 t; cvta.to.shared.u64 t, %1; cvt.u32.u64 %0, t; }"
        : "=r"(a) : "l"(p));
    return a;
}

__device__ __forceinline__ void cpa16(uint32_t dst, const void* src) {
    asm volatile("cp.async.cg.shared.global [%0], [%1], 16;"
                 :: "r"(dst), "l"(src) : "memory");
}
#define CPA_COMMIT() asm volatile("cp.async.commit_group;" ::: "memory")
#define CPA_WAIT1()  asm volatile("cp.async.wait_group 1;" ::: "memory")
#define CPA_WAIT0()  asm volatile("cp.async.wait_group 0;" ::: "memory")

// ---------------- pre-pass: k-column 8-group interleave + tf32 round -------
// new layout per 8-group: [old0, old4, old1, old5, old2, old6, old3, old7]
struct PArgs {
    const float* in[7];
    float* out[7];
    int n8[7];
};

__global__ __launch_bounds__(256) void permute_round(PArgs pa)
{
    const int z = blockIdx.y;
    const int i = blockIdx.x * 256 + threadIdx.x;
    if (i >= pa.n8[z]) return;
    const float4* src = (const float4*)pa.in[z] + 2 * (size_t)i;
    float4 lo = src[0], hi = src[1];
    float4 o0, o1;
    o0.x = cvt_tf32f(lo.x);  // new0 = old0
    o0.y = cvt_tf32f(hi.x);  // new1 = old4
    o0.z = cvt_tf32f(lo.y);  // new2 = old1
    o0.w = cvt_tf32f(hi.y);  // new3 = old5
    o1.x = cvt_tf32f(lo.z);  // new4 = old2
    o1.y = cvt_tf32f(hi.z);  // new5 = old6
    o1.z = cvt_tf32f(lo.w);  // new6 = old3
    o1.w = cvt_tf32f(hi.w);  // new7 = old7
    float4* dst = (float4*)pa.out[z] + 2 * (size_t)i;
    dst[0] = o0; dst[1] = o1;
}

// ---------------- GEMM (tf32 mma, LDS.64 frags, no cvt): Y = X @ W^T + b ---
// R13 config: CTA 128x128x32, 128 threads = 4 warps (2m x 2n), warp tile 64x64.
// 2-stage cp.async, 1 sync/iter.
// mode 0: plain [M,N] fp32 (O projection)
// mode 2: [B,H,Dh,S], S 8-group interleaved, tf32 (V)
// mode 3: Q/K layout + S-row 8-group interleave (K)
// mode 4: [B,H,S,Dh], Dh 8-group interleaved, tf32, scaled by QSC (Q)
#define GP 40
#define G_STAGE 10240
#define G_BOFF  5120
#define G_SMEM_FLOATS (2 * G_STAGE)     // 81920 bytes

struct GArgs {
    const float* X[3];
    const float* W[3];
    const float* bias[3];
    float*       Y[3];
    int mode[3];
};

__global__ __launch_bounds__(128) void gemm_tf32(GArgs ga)
{
    extern __shared__ float sg[];
    const uint32_t smb = smem_u32(sg);

    const int z = blockIdx.z;
    const float* __restrict__ X    = ga.X[z];
    const float* __restrict__ W    = ga.W[z];
    const float* __restrict__ bias = ga.bias[z];
    float* __restrict__       Y    = ga.Y[z];
    const int mode = ga.mode[z];

    const int t    = threadIdx.x;
    const int lane = t & 31;
    const int wid  = t >> 5;
    const int gid  = lane >> 2;
    const int tg   = lane & 3;

    const int bm = blockIdx.y * 128;
    const int bn = blockIdx.x * 128;
    const int m_base = (wid >> 1) * 64;
    const int n_base = (wid & 1) * 64;

    float acc[4][8][4];
    #pragma unroll
    for (int mt = 0; mt < 4; mt++)
        #pragma unroll
        for (int nt = 0; nt < 8; nt++)
            #pragma unroll
            for (int i = 0; i < 4; i++) acc[mt][nt][i] = 0.f;

    {
        const float* xs = X + (size_t)bm * DMODEL;
        const float* ws = W + (size_t)bn * DMODEL;
        #pragma unroll
        for (int l = 0; l < 8; l++) {
            int id = t + 128 * l;
            int r  = id >> 3, q = id & 7;
            cpa16(smb + (uint32_t)(r * GP + q * 4) * 4,
                  xs + (size_t)r * DMODEL + q * 4);
            cpa16(smb + (uint32_t)(G_BOFF + r * GP + q * 4) * 4,
                  ws + (size_t)r * DMODEL + q * 4);
        }
        CPA_COMMIT();
    }

    for (int c = 0; c < 32; c++) {
        CPA_WAIT0();
        __syncthreads();

        if (c + 1 < 32) {
            const int naof = ((c + 1) & 1) * G_STAGE;
            const int k0   = (c + 1) * 32;
            const float* xs = X + (size_t)bm * DMODEL + k0;
            const float* ws = W + (size_t)bn * DMODEL + k0;
            #pragma unroll
            for (int l = 0; l < 8; l++) {
                int id = t + 128 * l;
                int r  = id >> 3, q = id & 7;
                cpa16(smb + (uint32_t)(naof + r * GP + q * 4) * 4,
                      xs + (size_t)r * DMODEL + q * 4);
                cpa16(smb + (uint32_t)(naof + G_BOFF + r * GP + q * 4) * 4,
                      ws + (size_t)r * DMODEL + q * 4);
            }
            CPA_COMMIT();
        }

        const float* As = sg + (c & 1) * G_STAGE;
        const float* Bs = As + G_BOFF;
        #pragma unroll
        for (int ks = 0; ks < 4; ks++) {
            const int kb = ks * 8;
            unsigned afr[4][4];
            #pragma unroll
            for (int mt = 0; mt < 4; mt++) {
                int m = m_base + mt * 16;
                float2 a0 = *(const float2*)&As[(m + gid    ) * GP + kb + 2 * tg];
                float2 a1 = *(const float2*)&As[(m + gid + 8) * GP + kb + 2 * tg];
                afr[mt][0] = __float_as_uint(a0.x);
                afr[mt][1] = __float_as_uint(a1.x);
                afr[mt][2] = __float_as_uint(a0.y);
                afr[mt][3] = __float_as_uint(a1.y);
            }
            unsigned bfr[8][2];
            #pragma unroll
            for (int nt = 0; nt < 8; nt++) {
                int n = n_base + nt * 8;
                float2 bb = *(const float2*)&Bs[(n + gid) * GP + kb + 2 * tg];
                bfr[nt][0] = __float_as_uint(bb.x);
                bfr[nt][1] = __float_as_uint(bb.y);
            }
            #pragma unroll
            for (int mt = 0; mt < 4; mt++)
                #pragma unroll
                for (int nt = 0; nt < 8; nt++)
                    mma_tf32(acc[mt][nt], afr[mt], bfr[nt]);
        }
    }

    // epilogue
    #pragma unroll
    for (int nt = 0; nt < 8; nt++) {
        int c0 = bn + n_base + nt * 8 + tg * 2;
        float b0 = bias[c0], b1 = bias[c0 + 1];
        #pragma unroll
        for (int mt = 0; mt < 4; mt++) {
            int r0 = bm + m_base + mt * 16 + gid;
            #pragma unroll
            for (int half = 0; half < 2; half++) {
                int m = r0 + half * 8;
                float v0 = acc[mt][nt][half * 2 + 0] + b0;
                float v1 = acc[mt][nt][half * 2 + 1] + b1;
                if (mode == 0) {
                    Y[(size_t)m * DMODEL + c0]     = v0;
                    Y[(size_t)m * DMODEL + c0 + 1] = v1;
                } else if (mode == 3 || mode == 4) {
                    if (mode == 4) { v0 *= QSC; v1 *= QSC; }   // Q pre-scale
                    int b_ = m >> 11;
                    int s  = m & (SEQ - 1);
                    if (mode == 3) s = (s & ~7) + perm8(s & 7);   // K: row perm
                    int h  = c0 >> 6;
                    int dh = c0 & (DHEAD - 1);
                    int g8 = dh & ~7, o = dh & 7;
                    size_t base = (((size_t)(b_ * NHEADS + h)) * SEQ + s) * DHEAD + g8;
                    Y[base + perm8(o)]     = cvt_tf32f(v0);
                    Y[base + perm8(o + 1)] = cvt_tf32f(v1);
                } else {
                    int b_ = m >> 11;
                    int s  = m & (SEQ - 1);
                    int h  = c0 >> 6;
                    int dh = c0 & (DHEAD - 1);
                    int sp = (s & ~7) + perm8(s & 7);
                    size_t base = (((size_t)(b_ * NHEADS + h)) * DHEAD + dh) * SEQ + sp;
                    Y[base]       = cvt_tf32f(v0);
                    Y[base + SEQ] = cvt_tf32f(v1);
                }
            }
        }
    }
}

// ---------------- attention: register flash, shuffle-free PV ---------------
// Q: dh-interleaved, PRE-SCALED tf32 in gmem -> fragments loaded directly
// via LDG (no smem staging, no extra syncs). K: dh + s-row interleaved
// (QK c-frag holds kv {tg, tg+4} -> direct PV a-frag reuse). V: [B,H,Dh,S].
#define KP 72
#define VP 72
#define A_STAGE 9216
#define A_SMEM_FLOATS (3 * A_STAGE)     // 110592 bytes

__global__ __launch_bounds__(256) void attn_kernel(
    const float* __restrict__ Q, const float* __restrict__ K,
    const float* __restrict__ V, float* __restrict__ O)
{
    extern __shared__ float sm[];
    const uint32_t smb = smem_u32(sm);

    const int t    = threadIdx.x;
    const int lane = t & 31;
    const int wid  = t >> 5;
    const int gid  = lane >> 2;
    const int tg   = lane & 3;

    const int b  = blockIdx.z, h = blockIdx.y;
    const int q0 = blockIdx.x << 7;
    const size_t head_base = ((size_t)(b * NHEADS + h)) * SEQ * DHEAD;

    // ---- prefetch KV tiles 0,1 immediately (no Q staging to wait for) ----
    #pragma unroll
    for (int p = 0; p < 2; p++) {
        const int koff = p * A_STAGE;
        const int voff = p * A_STAGE + 4608;
        #pragma unroll
        for (int l = 0; l < 4; l++) {
            int id = t + 256 * l;
            int r  = id >> 4;
            int c4 = (id & 15) << 2;
            cpa16(smb + (uint32_t)(koff + r * KP + c4) * 4,
                  K + head_base + (size_t)(p * 64 + r) * DHEAD + c4);
            cpa16(smb + (uint32_t)(voff + r * VP + c4) * 4,
                  V + head_base + (size_t)r * SEQ + p * 64 + c4);
        }
        CPA_COMMIT();
    }

    // ---- load Q fragments directly from gmem (pre-scaled tf32 bits) ----
    unsigned qf[8][4];
    {
        const int wrow = wid * 16;
        const float* qrow0 = Q + head_base + (size_t)(q0 + wrow + gid) * DHEAD;
        const float* qrow1 = qrow0 + 8 * DHEAD;
        #pragma unroll
        for (int ks = 0; ks < 8; ks++) {
            const int kb = ks * 8 + 2 * tg;
            float2 qa = *(const float2*)&qrow0[kb];
            float2 qb = *(const float2*)&qrow1[kb];
            qf[ks][0] = __float_as_uint(qa.x);
            qf[ks][1] = __float_as_uint(qb.x);
            qf[ks][2] = __float_as_uint(qa.y);
            qf[ks][3] = __float_as_uint(qb.y);
        }
    }

    float oacc[8][4];
    #pragma unroll
    for (int nt = 0; nt < 8; nt++)
        #pragma unroll
        for (int i = 0; i < 4; i++) oacc[nt][i] = 0.f;
    float m0 = -1e30f, m1 = -1e30f, l0 = 0.f, l1 = 0.f;

    const int NIT = SEQ / 64;   // 32
    for (int it = 0; it < NIT; it++) {
        if (it + 1 < NIT) { CPA_WAIT1(); } else { CPA_WAIT0(); }
        __syncthreads();

        if (it + 2 < NIT) {
            const int ns = (it + 2) % 3;
            const int nk = ns * A_STAGE;
            const int nv = ns * A_STAGE + 4608;
            #pragma unroll
            for (int l = 0; l < 4; l++) {
                int id = t + 256 * l;
                int r  = id >> 4;
                int c4 = (id & 15) << 2;
                cpa16(smb + (uint32_t)(nk + r * KP + c4) * 4,
                      K + head_base + (size_t)((it + 2) * 64 + r) * DHEAD + c4);
                cpa16(smb + (uint32_t)(nv + r * VP + c4) * 4,
                      V + head_base + (size_t)r * SEQ + (it + 2) * 64 + c4);
            }
            CPA_COMMIT();
        }

        const int stage = it % 3;
        const float* Ks = sm + stage * A_STAGE;
        const float* Vs = sm + stage * A_STAGE + 4608;

        // ---- S2 = (Q*0.125*log2e) K^T (K s-rows permuted: c-frag = kv {tg,tg+4}) ----
        float sacc[8][4];
        #pragma unroll
        for (int nt = 0; nt < 8; nt++)
            #pragma unroll
            for (int i = 0; i < 4; i++) sacc[nt][i] = 0.f;

        #pragma unroll
        for (int ks = 0; ks < 8; ks++) {
            const int kb = ks * 8;
            unsigned bfr[8][2];
            #pragma unroll
            for (int nt = 0; nt < 8; nt++) {
                float2 kk = *(const float2*)&Ks[(nt * 8 + gid) * KP + kb + 2 * tg];
                bfr[nt][0] = __float_as_uint(kk.x);
                bfr[nt][1] = __float_as_uint(kk.y);
            }
            #pragma unroll
            for (int nt = 0; nt < 8; nt++)
                mma_tf32(sacc[nt], qf[ks], bfr[nt]);
        }

        // ---- online softmax, base-2, single-op EX2 ----
        float mx0 = -1e30f, mx1 = -1e30f;
        #pragma unroll
        for (int nt = 0; nt < 8; nt++) {
            mx0 = fmaxf(mx0, fmaxf(sacc[nt][0], sacc[nt][1]));
            mx1 = fmaxf(mx1, fmaxf(sacc[nt][2], sacc[nt][3]));
        }
        mx0 = fmaxf(mx0, __shfl_xor_sync(0xffffffffu, mx0, 1));
        mx0 = fmaxf(mx0, __shfl_xor_sync(0xffffffffu, mx0, 2));
        mx1 = fmaxf(mx1, __shfl_xor_sync(0xffffffffu, mx1, 1));
        mx1 = fmaxf(mx1, __shfl_xor_sync(0xffffffffu, mx1, 2));

        float m0n = fmaxf(m0, mx0), m1n = fmaxf(m1, mx1);
        float sc0 = ex2f(m0 - m0n), sc1 = ex2f(m1 - m1n);
        m0 = m0n; m1 = m1n;

        float s0 = 0.f, s1 = 0.f;
        #pragma unroll
        for (int nt = 0; nt < 8; nt++) {
            sacc[nt][0] = ex2f(sacc[nt][0] - m0); s0 += sacc[nt][0];
            sacc[nt][1] = ex2f(sacc[nt][1] - m0); s0 += sacc[nt][1];
            sacc[nt][2] = ex2f(sacc[nt][2] - m1); s1 += sacc[nt][2];
            sacc[nt][3] = ex2f(sacc[nt][3] - m1); s1 += sacc[nt][3];
        }
        s0 += __shfl_xor_sync(0xffffffffu, s0, 1);
        s0 += __shfl_xor_sync(0xffffffffu, s0, 2);
        s1 += __shfl_xor_sync(0xffffffffu, s1, 1);
        s1 += __shfl_xor_sync(0xffffffffu, s1, 2);
        l0 = l0 * sc0 + s0;
        l1 = l1 * sc1 + s1;

        #pragma unroll
        for (int nt = 0; nt < 8; nt++) {
            oacc[nt][0] *= sc0; oacc[nt][1] *= sc0;
            oacc[nt][2] *= sc1; oacc[nt][3] *= sc1;
        }

        // ---- PV: a-frags are direct register renames of sacc ----
        #pragma unroll
        for (int ks = 0; ks < 8; ks++) {
            unsigned a[4];
            a[0] = __float_as_uint(sacc[ks][0]);
            a[1] = __float_as_uint(sacc[ks][2]);
            a[2] = __float_as_uint(sacc[ks][1]);
            a[3] = __float_as_uint(sacc[ks][3]);

            const int kb = ks * 8;
            #pragma unroll
            for (int nt = 0; nt < 8; nt++) {
                float2 vv = *(const float2*)&Vs[(nt * 8 + gid) * VP + kb + 2 * tg];
                unsigned b2[2];
                b2[0] = __float_as_uint(vv.x);
                b2[1] = __float_as_uint(vv.y);
                mma_tf32(oacc[nt], a, b2);
            }
        }
    }

    // ---- epilogue: normalize, write k-interleaved rounded [B,S,D] ----
    {
        float il0 = 1.0f / l0, il1 = 1.0f / l1;
        int r0 = q0 + wid * 16 + gid;
        int r1 = r0 + 8;
        const int o = tg * 2;
        const int p0i = perm8(o), p1i = perm8(o + 1);
        #pragma unroll
        for (int nt = 0; nt < 8; nt++) {
            int cbase = h * DHEAD + nt * 8;
            size_t base0 = ((size_t)(b * SEQ + r0)) * DMODEL + cbase;
            size_t base1 = ((size_t)(b * SEQ + r1)) * DMODEL + cbase;
            O[base0 + p0i] = cvt_tf32f(oacc[nt][0] * il0);
            O[base0 + p1i] = cvt_tf32f(oacc[nt][1] * il0);
            O[base1 + p0i] = cvt_tf32f(oacc[nt][2] * il1);
            O[base1 + p1i] = cvt_tf32f(oacc[nt][3] * il1);
        }
    }
}

extern "C" void kernel_launch(void* const* d_in, const int* in_sizes, int n_in,
                              void* d_out, int out_size)
{
    const float* query = (const float*)d_in[0];
    const float* key_  = (const float*)d_in[1];
    const float* value = (const float*)d_in[2];
    const float* Wq = (const float*)d_in[3];
    const float* bq = (const float*)d_in[4];
    const float* Wk = (const float*)d_in[5];
    const float* bk = (const float*)d_in[6];
    const float* Wv = (const float*)d_in[7];
    const float* bv = (const float*)d_in[8];
    const float* Wo = (const float*)d_in[9];
    const float* bo = (const float*)d_in[10];

    float *qptr, *kptr, *vptr, *aoptr, *rxptr, *rwptr;
    cudaGetSymbolAddress((void**)&qptr,  g_q);
    cudaGetSymbolAddress((void**)&kptr,  g_k);
    cudaGetSymbolAddress((void**)&vptr,  g_v);
    cudaGetSymbolAddress((void**)&aoptr, g_ao);
    cudaGetSymbolAddress((void**)&rxptr, g_rx);
    cudaGetSymbolAddress((void**)&rwptr, g_rw);

    float* rq  = rxptr;
    float* rk  = rxptr + (size_t)MROWS * DMODEL;
    float* rv  = rxptr + 2 * (size_t)MROWS * DMODEL;
    float* rwq = rwptr;
    float* rwk = rwptr + (size_t)DMODEL * DMODEL;
    float* rwv = rwptr + 2 * (size_t)DMODEL * DMODEL;
    float* rwo = rwptr + 3 * (size_t)DMODEL * DMODEL;

    const int gemm_smem = G_SMEM_FLOATS * sizeof(float);   // 81920
    const int attn_smem = A_SMEM_FLOATS * sizeof(float);   // 110592
    cudaFuncSetAttribute(gemm_tf32, cudaFuncAttributeMaxDynamicSharedMemorySize, gemm_smem);
    cudaFuncSetAttribute(attn_kernel, cudaFuncAttributeMaxDynamicSharedMemorySize, attn_smem);

    // one fused pre-pass: k-permute (8-group) + tf32-round all 7 GEMM operands
    PArgs pa;
    pa.in[0] = query; pa.out[0] = rq;  pa.n8[0] = MROWS * DMODEL / 8;
    pa.in[1] = key_;  pa.out[1] = rk;  pa.n8[1] = MROWS * DMODEL / 8;
    pa.in[2] = value; pa.out[2] = rv;  pa.n8[2] = MROWS * DMODEL / 8;
    pa.in[3] = Wq;    pa.out[3] = rwq; pa.n8[3] = DMODEL * DMODEL / 8;
    pa.in[4] = Wk;    pa.out[4] = rwk; pa.n8[4] = DMODEL * DMODEL / 8;
    pa.in[5] = Wv;    pa.out[5] = rwv; pa.n8[5] = DMODEL * DMODEL / 8;
    pa.in[6] = Wo;    pa.out[6] = rwo; pa.n8[6] = DMODEL * DMODEL / 8;
    dim3 pgrid((MROWS * DMODEL / 8 + 255) / 256, 7);
    permute_round<<<pgrid, 256>>>(pa);

    // fused QKV projections (grid.z selects matrix)
    GArgs qkv;
    qkv.X[0] = rq; qkv.W[0] = rwq; qkv.bias[0] = bq; qkv.Y[0] = qptr; qkv.mode[0] = 4;
    qkv.X[1] = rk; qkv.W[1] = rwk; qkv.bias[1] = bk; qkv.Y[1] = kptr; qkv.mode[1] = 3;
    qkv.X[2] = rv; qkv.W[2] = rwv; qkv.bias[2] = bv; qkv.Y[2] = vptr; qkv.mode[2] = 2;
    dim3 qkvgrid(DMODEL / 128, MROWS / 128, 3);   // (8, 32, 3)
    gemm_tf32<<<qkvgrid, 128, gemm_smem>>>(qkv);

    dim3 agrid(SEQ / 128, NHEADS, BATCH);         // (16, 16, 2)
    attn_kernel<<<agrid, 256, attn_smem>>>(qptr, kptr, vptr, aoptr);

    GArgs og;
    og.X[0] = aoptr; og.W[0] = rwo; og.bias[0] = bo; og.Y[0] = (float*)d_out; og.mode[0] = 0;
    og.X[1] = aoptr; og.W[1] = rwo; og.bias[1] = bo; og.Y[1] = (float*)d_out; og.mode[1] = 0;
    og.X[2] = aoptr; og.W[2] = rwo; og.bias[2] = bo; og.Y[2] = (float*)d_out; og.mode[2] = 0;
    dim3 ogrid(DMODEL / 128, MROWS / 128, 1);     // (8, 32, 1)
    gemm_tf32<<<ogrid, 128, gemm_smem>>>(og);
}

// round 17
// speedup vs baseline: 1.0457x; 1.0072x over previous
#include <cuda_runtime.h>
#include <cstddef>
#include <cstdint>

// Problem constants
#define BATCH 2
#define SEQ   2048
#define DMODEL 1024
#define NHEADS 16
#define DHEAD 64
#define MROWS (BATCH*SEQ)        // 4096

#define LOG2E 1.44269504088896340736f
#define QSC  (0.125f * LOG2E)

// ---------------- scratch (no allocation allowed) ----------------
// g_q: [B,H,S,Dh] Dh 8-group interleaved, PRE-SCALED by 0.125*log2e (tf32)
// g_k: [B,H,S,Dh] Dh 8-group interleaved AND S-rows 8-group interleaved (tf32)
// g_v: [B,H,Dh,S] S 8-group interleaved (tf32)
// g_ao: [M, DMODEL] k-columns 8-group interleaved, tf32 (O-GEMM A-side)
__device__ float g_q[BATCH*NHEADS*SEQ*DHEAD];
__device__ float g_k[BATCH*NHEADS*SEQ*DHEAD];
__device__ float g_v[BATCH*NHEADS*SEQ*DHEAD];
__device__ float g_ao[MROWS*DMODEL];
// k-permuted + tf32-rounded copies of inputs
__device__ float g_rx[3][MROWS*DMODEL];         // query/key_/value
__device__ float g_rw[4][DMODEL*DMODEL];        // Wq/Wk/Wv/Wo

// ---------------- helpers ----------------
__device__ __forceinline__ float cvt_tf32f(float x) {
    unsigned u;
    asm("cvt.rna.tf32.f32 %0, %1;" : "=r"(u) : "f"(x));
    return __uint_as_float(u);
}

__device__ __forceinline__ float ex2f(float x) {
    float y;
    asm("ex2.approx.ftz.f32 %0, %1;" : "=f"(y) : "f"(x));
    return y;
}

// interleave within 8-group: old offset o -> new position
__device__ __forceinline__ int perm8(int o) {
    return (o < 4) ? (2 * o) : (2 * o - 7);
}

__device__ __forceinline__ void mma_tf32(float* c, const unsigned* a, const unsigned* b) {
    asm volatile(
        "mma.sync.aligned.m16n8k8.row.col.f32.tf32.tf32.f32 "
        "{%0,%1,%2,%3}, {%4,%5,%6,%7}, {%8,%9}, {%0,%1,%2,%3};"
        : "+f"(c[0]), "+f"(c[1]), "+f"(c[2]), "+f"(c[3])
        : "r"(a[0]), "r"(a[1]), "r"(a[2]), "r"(a[3]),
          "r"(b[0]), "r"(b[1]));
}

__device__ __forceinline__ uint32_t smem_u32(const void* p) {
    uint32_t a;
    asm("{ .reg .u64 t; cvta.to.shared.u64 t, %1; cvt.u32.u64 %0, t; }"
        : "=r"(a) : "l"(p));
    return a;
}

__device__ __forceinline__ void cpa16(uint32_t dst, const void* src) {
    asm volatile("cp.async.cg.shared.global [%0], [%1], 16;"
                 :: "r"(dst), "l"(src) : "memory");
}
#define CPA_COMMIT() asm volatile("cp.async.commit_group;" ::: "memory")
#define CPA_WAIT1()  asm volatile("cp.async.wait_group 1;" ::: "memory")
#define CPA_WAIT0()  asm volatile("cp.async.wait_group 0;" ::: "memory")

// ---------------- pre-pass: k-column 8-group interleave + tf32 round -------
// new layout per 8-group: [old0, old4, old1, old5, old2, old6, old3, old7]
struct PArgs {
    const float* in[7];
    float* out[7];
    int n8[7];
};

__global__ __launch_bounds__(256) void permute_round(PArgs pa)
{
    const int z = blockIdx.y;
    const int i = blockIdx.x * 256 + threadIdx.x;
    if (i >= pa.n8[z]) return;
    const float4* src = (const float4*)pa.in[z] + 2 * (size_t)i;
    float4 lo = src[0], hi = src[1];
    float4 o0, o1;
    o0.x = cvt_tf32f(lo.x);  // new0 = old0
    o0.y = cvt_tf32f(hi.x);  // new1 = old4
    o0.z = cvt_tf32f(lo.y);  // new2 = old1
    o0.w = cvt_tf32f(hi.y);  // new3 = old5
    o1.x = cvt_tf32f(lo.z);  // new4 = old2
    o1.y = cvt_tf32f(hi.z);  // new5 = old6
    o1.z = cvt_tf32f(lo.w);  // new6 = old3
    o1.w = cvt_tf32f(hi.w);  // new7 = old7
    float4* dst = (float4*)pa.out[z] + 2 * (size_t)i;
    dst[0] = o0; dst[1] = o1;
}

// ---------------- GEMM (tf32 mma, LDS.64 frags, no cvt): Y = X @ W^T + b ---
// R13 config: CTA 128x128x32, 128 threads = 4 warps (2m x 2n), warp tile 64x64.
// 2-stage cp.async, 1 sync/iter.
// mode 0: plain [M,N] fp32 (O projection)
// mode 2: [B,H,Dh,S], S 8-group interleaved, tf32 (V)
// mode 3: Q/K layout + S-row 8-group interleave (K)
// mode 4: [B,H,S,Dh], Dh 8-group interleaved, tf32, scaled by QSC (Q)
#define GP 40
#define G_STAGE 10240
#define G_BOFF  5120
#define G_SMEM_FLOATS (2 * G_STAGE)     // 81920 bytes

struct GArgs {
    const float* X[3];
    const float* W[3];
    const float* bias[3];
    float*       Y[3];
    int mode[3];
};

__global__ __launch_bounds__(128) void gemm_tf32(GArgs ga)
{
    extern __shared__ float sg[];
    const uint32_t smb = smem_u32(sg);

    const int z = blockIdx.z;
    const float* __restrict__ X    = ga.X[z];
    const float* __restrict__ W    = ga.W[z];
    const float* __restrict__ bias = ga.bias[z];
    float* __restrict__       Y    = ga.Y[z];
    const int mode = ga.mode[z];

    const int t    = threadIdx.x;
    const int lane = t & 31;
    const int wid  = t >> 5;
    const int gid  = lane >> 2;
    const int tg   = lane & 3;

    const int bm = blockIdx.y * 128;
    const int bn = blockIdx.x * 128;
    const int m_base = (wid >> 1) * 64;
    const int n_base = (wid & 1) * 64;

    float acc[4][8][4];
    #pragma unroll
    for (int mt = 0; mt < 4; mt++)
        #pragma unroll
        for (int nt = 0; nt < 8; nt++)
            #pragma unroll
            for (int i = 0; i < 4; i++) acc[mt][nt][i] = 0.f;

    {
        const float* xs = X + (size_t)bm * DMODEL;
        const float* ws = W + (size_t)bn * DMODEL;
        #pragma unroll
        for (int l = 0; l < 8; l++) {
            int id = t + 128 * l;
            int r  = id >> 3, q = id & 7;
            cpa16(smb + (uint32_t)(r * GP + q * 4) * 4,
                  xs + (size_t)r * DMODEL + q * 4);
            cpa16(smb + (uint32_t)(G_BOFF + r * GP + q * 4) * 4,
                  ws + (size_t)r * DMODEL + q * 4);
        }
        CPA_COMMIT();
    }

    for (int c = 0; c < 32; c++) {
        CPA_WAIT0();
        __syncthreads();

        if (c + 1 < 32) {
            const int naof = ((c + 1) & 1) * G_STAGE;
            const int k0   = (c + 1) * 32;
            const float* xs = X + (size_t)bm * DMODEL + k0;
            const float* ws = W + (size_t)bn * DMODEL + k0;
            #pragma unroll
            for (int l = 0; l < 8; l++) {
                int id = t + 128 * l;
                int r  = id >> 3, q = id & 7;
                cpa16(smb + (uint32_t)(naof + r * GP + q * 4) * 4,
                      xs + (size_t)r * DMODEL + q * 4);
                cpa16(smb + (uint32_t)(naof + G_BOFF + r * GP + q * 4) * 4,
                      ws + (size_t)r * DMODEL + q * 4);
            }
            CPA_COMMIT();
        }

        const float* As = sg + (c & 1) * G_STAGE;
        const float* Bs = As + G_BOFF;
        #pragma unroll
        for (int ks = 0; ks < 4; ks++) {
            const int kb = ks * 8;
            unsigned afr[4][4];
            #pragma unroll
            for (int mt = 0; mt < 4; mt++) {
                int m = m_base + mt * 16;
                float2 a0 = *(const float2*)&As[(m + gid    ) * GP + kb + 2 * tg];
                float2 a1 = *(const float2*)&As[(m + gid + 8) * GP + kb + 2 * tg];
                afr[mt][0] = __float_as_uint(a0.x);
                afr[mt][1] = __float_as_uint(a1.x);
                afr[mt][2] = __float_as_uint(a0.y);
                afr[mt][3] = __float_as_uint(a1.y);
            }
            unsigned bfr[8][2];
            #pragma unroll
            for (int nt = 0; nt < 8; nt++) {
                int n = n_base + nt * 8;
                float2 bb = *(const float2*)&Bs[(n + gid) * GP + kb + 2 * tg];
                bfr[nt][0] = __float_as_uint(bb.x);
                bfr[nt][1] = __float_as_uint(bb.y);
            }
            #pragma unroll
            for (int mt = 0; mt < 4; mt++)
                #pragma unroll
                for (int nt = 0; nt < 8; nt++)
                    mma_tf32(acc[mt][nt], afr[mt], bfr[nt]);
        }
    }

    // epilogue
    #pragma unroll
    for (int nt = 0; nt < 8; nt++) {
        int c0 = bn + n_base + nt * 8 + tg * 2;
        float b0 = bias[c0], b1 = bias[c0 + 1];
        #pragma unroll
        for (int mt = 0; mt < 4; mt++) {
            int r0 = bm + m_base + mt * 16 + gid;
            #pragma unroll
            for (int half = 0; half < 2; half++) {
                int m = r0 + half * 8;
                float v0 = acc[mt][nt][half * 2 + 0] + b0;
                float v1 = acc[mt][nt][half * 2 + 1] + b1;
                if (mode == 0) {
                    Y[(size_t)m * DMODEL + c0]     = v0;
                    Y[(size_t)m * DMODEL + c0 + 1] = v1;
                } else if (mode == 3 || mode == 4) {
                    if (mode == 4) { v0 *= QSC; v1 *= QSC; }   // Q pre-scale
                    int b_ = m >> 11;
                    int s  = m & (SEQ - 1);
                    if (mode == 3) s = (s & ~7) + perm8(s & 7);   // K: row perm
                    int h  = c0 >> 6;
                    int dh = c0 & (DHEAD - 1);
                    int g8 = dh & ~7, o = dh & 7;
                    size_t base = (((size_t)(b_ * NHEADS + h)) * SEQ + s) * DHEAD + g8;
                    Y[base + perm8(o)]     = cvt_tf32f(v0);
                    Y[base + perm8(o + 1)] = cvt_tf32f(v1);
                } else {
                    int b_ = m >> 11;
                    int s  = m & (SEQ - 1);
                    int h  = c0 >> 6;
                    int dh = c0 & (DHEAD - 1);
                    int sp = (s & ~7) + perm8(s & 7);
                    size_t base = (((size_t)(b_ * NHEADS + h)) * DHEAD + dh) * SEQ + sp;
                    Y[base]       = cvt_tf32f(v0);
                    Y[base + SEQ] = cvt_tf32f(v1);
                }
            }
        }
    }
}

// ---------------- attention: register flash, shuffle-free PV ---------------
// Q: dh-interleaved, pre-scaled+rounded in gmem -> pure-copy staging into
// KV stage 2's region (overlapped with KV tile 0/1 prefetch, 1 pre-loop sync).
// K: dh + s-row interleaved (QK c-frag = kv {tg,tg+4} -> direct PV a-frag).
// V: [B,H,Dh,S] s-interleaved. Deferred l quad-reduction.
#define KP 72
#define VP 72
#define A_STAGE 9216
#define A_SMEM_FLOATS (3 * A_STAGE)     // 110592 bytes

__global__ __launch_bounds__(256) void attn_kernel(
    const float* __restrict__ Q, const float* __restrict__ K,
    const float* __restrict__ V, float* __restrict__ O)
{
    extern __shared__ float sm[];
    const uint32_t smb = smem_u32(sm);

    const int t    = threadIdx.x;
    const int lane = t & 31;
    const int wid  = t >> 5;
    const int gid  = lane >> 2;
    const int tg   = lane & 3;

    const int b  = blockIdx.z, h = blockIdx.y;
    const int q0 = blockIdx.x << 7;
    const size_t head_base = ((size_t)(b * NHEADS + h)) * SEQ * DHEAD;

    // ---- issue KV prefetch for tiles 0,1 first (stages 0,1) ----
    #pragma unroll
    for (int p = 0; p < 2; p++) {
        const int koff = p * A_STAGE;
        const int voff = p * A_STAGE + 4608;
        #pragma unroll
        for (int l = 0; l < 4; l++) {
            int id = t + 256 * l;
            int r  = id >> 4;
            int c4 = (id & 15) << 2;
            cpa16(smb + (uint32_t)(koff + r * KP + c4) * 4,
                  K + head_base + (size_t)(p * 64 + r) * DHEAD + c4);
            cpa16(smb + (uint32_t)(voff + r * VP + c4) * 4,
                  V + head_base + (size_t)r * SEQ + p * 64 + c4);
        }
        CPA_COMMIT();
    }

    // ---- stage Q into stage-2 region (pure copy; overlaps KV prefetch) ----
    {
        float (*Qs)[KP] = (float (*)[KP])(sm + 2 * A_STAGE);
        #pragma unroll
        for (int l = 0; l < 8; l++) {
            int id = t + 256 * l;
            int r  = id >> 4;
            int d4 = (id & 15) << 2;
            float4 v = *(const float4*)&Q[head_base + (size_t)(q0 + r) * DHEAD + d4];
            *(float4*)&Qs[r][d4] = v;
        }
    }
    __syncthreads();

    unsigned qf[8][4];
    {
        float (*Qs)[KP] = (float (*)[KP])(sm + 2 * A_STAGE);
        const int wrow = wid * 16;
        #pragma unroll
        for (int ks = 0; ks < 8; ks++) {
            const int kb = ks * 8;
            float2 qa = *(const float2*)&Qs[wrow + gid    ][kb + 2 * tg];
            float2 qb = *(const float2*)&Qs[wrow + gid + 8][kb + 2 * tg];
            qf[ks][0] = __float_as_uint(qa.x);
            qf[ks][1] = __float_as_uint(qb.x);
            qf[ks][2] = __float_as_uint(qa.y);
            qf[ks][3] = __float_as_uint(qb.y);
        }
    }
    // NOTE: no sync here — the iter-0 barrier below orders all threads' qf
    // extraction before the tile-2 prefetch that overwrites stage 2.

    float oacc[8][4];
    #pragma unroll
    for (int nt = 0; nt < 8; nt++)
        #pragma unroll
        for (int i = 0; i < 4; i++) oacc[nt][i] = 0.f;
    float m0 = -1e30f, m1 = -1e30f, l0 = 0.f, l1 = 0.f;   // l: lane-local partial

    const int NIT = SEQ / 64;   // 32
    for (int it = 0; it < NIT; it++) {
        if (it + 1 < NIT) { CPA_WAIT1(); } else { CPA_WAIT0(); }
        __syncthreads();

        if (it + 2 < NIT) {
            const int ns = (it + 2) % 3;
            const int nk = ns * A_STAGE;
            const int nv = ns * A_STAGE + 4608;
            #pragma unroll
            for (int l = 0; l < 4; l++) {
                int id = t + 256 * l;
                int r  = id >> 4;
                int c4 = (id & 15) << 2;
                cpa16(smb + (uint32_t)(nk + r * KP + c4) * 4,
                      K + head_base + (size_t)((it + 2) * 64 + r) * DHEAD + c4);
                cpa16(smb + (uint32_t)(nv + r * VP + c4) * 4,
                      V + head_base + (size_t)r * SEQ + (it + 2) * 64 + c4);
            }
            CPA_COMMIT();
        }

        const int stage = it % 3;
        const float* Ks = sm + stage * A_STAGE;
        const float* Vs = sm + stage * A_STAGE + 4608;

        // ---- S2 = (Q*0.125*log2e) K^T (K s-rows permuted: c-frag = kv {tg,tg+4}) ----
        float sacc[8][4];
        #pragma unroll
        for (int nt = 0; nt < 8; nt++)
            #pragma unroll
            for (int i = 0; i < 4; i++) sacc[nt][i] = 0.f;

        #pragma unroll
        for (int ks = 0; ks < 8; ks++) {
            const int kb = ks * 8;
            unsigned bfr[8][2];
            #pragma unroll
            for (int nt = 0; nt < 8; nt++) {
                float2 kk = *(const float2*)&Ks[(nt * 8 + gid) * KP + kb + 2 * tg];
                bfr[nt][0] = __float_as_uint(kk.x);
                bfr[nt][1] = __float_as_uint(kk.y);
            }
            #pragma unroll
            for (int nt = 0; nt < 8; nt++)
                mma_tf32(sacc[nt], qf[ks], bfr[nt]);
        }

        // ---- online softmax, base-2, single-op EX2 ----
        float mx0 = -1e30f, mx1 = -1e30f;
        #pragma unroll
        for (int nt = 0; nt < 8; nt++) {
            mx0 = fmaxf(mx0, fmaxf(sacc[nt][0], sacc[nt][1]));
            mx1 = fmaxf(mx1, fmaxf(sacc[nt][2], sacc[nt][3]));
        }
        mx0 = fmaxf(mx0, __shfl_xor_sync(0xffffffffu, mx0, 1));
        mx0 = fmaxf(mx0, __shfl_xor_sync(0xffffffffu, mx0, 2));
        mx1 = fmaxf(mx1, __shfl_xor_sync(0xffffffffu, mx1, 1));
        mx1 = fmaxf(mx1, __shfl_xor_sync(0xffffffffu, mx1, 2));

        float m0n = fmaxf(m0, mx0), m1n = fmaxf(m1, mx1);
        float sc0 = ex2f(m0 - m0n), sc1 = ex2f(m1 - m1n);
        m0 = m0n; m1 = m1n;

        float s0 = 0.f, s1 = 0.f;
        #pragma unroll
        for (int nt = 0; nt < 8; nt++) {
            sacc[nt][0] = ex2f(sacc[nt][0] - m0); s0 += sacc[nt][0];
            sacc[nt][1] = ex2f(sacc[nt][1] - m0); s0 += sacc[nt][1];
            sacc[nt][2] = ex2f(sacc[nt][2] - m1); s1 += sacc[nt][2];
            sacc[nt][3] = ex2f(sacc[nt][3] - m1); s1 += sacc[nt][3];
        }
        // deferred l reduction: sc is quad-uniform, so lane-local partials
        // can be accumulated and quad-reduced once after the loop.
        l0 = l0 * sc0 + s0;
        l1 = l1 * sc1 + s1;

        #pragma unroll
        for (int nt = 0; nt < 8; nt++) {
            oacc[nt][0] *= sc0; oacc[nt][1] *= sc0;
            oacc[nt][2] *= sc1; oacc[nt][3] *= sc1;
        }

        // ---- PV: a-frags are direct register renames of sacc ----
        #pragma unroll
        for (int ks = 0; ks < 8; ks++) {
            unsigned a[4];
            a[0] = __float_as_uint(sacc[ks][0]);
            a[1] = __float_as_uint(sacc[ks][2]);
            a[2] = __float_as_uint(sacc[ks][1]);
            a[3] = __float_as_uint(sacc[ks][3]);

            const int kb = ks * 8;
            #pragma unroll
            for (int nt = 0; nt < 8; nt++) {
                float2 vv = *(const float2*)&Vs[(nt * 8 + gid) * VP + kb + 2 * tg];
                unsigned b2[2];
                b2[0] = __float_as_uint(vv.x);
                b2[1] = __float_as_uint(vv.y);
                mma_tf32(oacc[nt], a, b2);
            }
        }
    }

    // ---- final quad-reduction of l, then epilogue ----
    l0 += __shfl_xor_sync(0xffffffffu, l0, 1);
    l0 += __shfl_xor_sync(0xffffffffu, l0, 2);
    l1 += __shfl_xor_sync(0xffffffffu, l1, 1);
    l1 += __shfl_xor_sync(0xffffffffu, l1, 2);
    {
        float il0 = 1.0f / l0, il1 = 1.0f / l1;
        int r0 = q0 + wid * 16 + gid;
        int r1 = r0 + 8;
        const int o = tg * 2;
        const int p0i = perm8(o), p1i = perm8(o + 1);
        #pragma unroll
        for (int nt = 0; nt < 8; nt++) {
            int cbase = h * DHEAD + nt * 8;
            size_t base0 = ((size_t)(b * SEQ + r0)) * DMODEL + cbase;
            size_t base1 = ((size_t)(b * SEQ + r1)) * DMODEL + cbase;
            O[base0 + p0i] = cvt_tf32f(oacc[nt][0] * il0);
            O[base0 + p1i] = cvt_tf32f(oacc[nt][1] * il0);
            O[base1 + p0i] = cvt_tf32f(oacc[nt][2] * il1);
            O[base1 + p1i] = cvt_tf32f(oacc[nt][3] * il1);
        }
    }
}

extern "C" void kernel_launch(void* const* d_in, const int* in_sizes, int n_in,
                              void* d_out, int out_size)
{
    const float* query = (const float*)d_in[0];
    const float* key_  = (const float*)d_in[1];
    const float* value = (const float*)d_in[2];
    const float* Wq = (const float*)d_in[3];
    const float* bq = (const float*)d_in[4];
    const float* Wk = (const float*)d_in[5];
    const float* bk = (const float*)d_in[6];
    const float* Wv = (const float*)d_in[7];
    const float* bv = (const float*)d_in[8];
    const float* Wo = (const float*)d_in[9];
    const float* bo = (const float*)d_in[10];

    float *qptr, *kptr, *vptr, *aoptr, *rxptr, *rwptr;
    cudaGetSymbolAddress((void**)&qptr,  g_q);
    cudaGetSymbolAddress((void**)&kptr,  g_k);
    cudaGetSymbolAddress((void**)&vptr,  g_v);
    cudaGetSymbolAddress((void**)&aoptr, g_ao);
    cudaGetSymbolAddress((void**)&rxptr, g_rx);
    cudaGetSymbolAddress((void**)&rwptr, g_rw);

    float* rq  = rxptr;
    float* rk  = rxptr + (size_t)MROWS * DMODEL;
    float* rv  = rxptr + 2 * (size_t)MROWS * DMODEL;
    float* rwq = rwptr;
    float* rwk = rwptr + (size_t)DMODEL * DMODEL;
    float* rwv = rwptr + 2 * (size_t)DMODEL * DMODEL;
    float* rwo = rwptr + 3 * (size_t)DMODEL * DMODEL;

    const int gemm_smem = G_SMEM_FLOATS * sizeof(float);   // 81920
    const int attn_smem = A_SMEM_FLOATS * sizeof(float);   // 110592
    cudaFuncSetAttribute(gemm_tf32, cudaFuncAttributeMaxDynamicSharedMemorySize, gemm_smem);
    cudaFuncSetAttribute(attn_kernel, cudaFuncAttributeMaxDynamicSharedMemorySize, attn_smem);

    // one fused pre-pass: k-permute (8-group) + tf32-round all 7 GEMM operands
    PArgs pa;
    pa.in[0] = query; pa.out[0] = rq;  pa.n8[0] = MROWS * DMODEL / 8;
    pa.in[1] = key_;  pa.out[1] = rk;  pa.n8[1] = MROWS * DMODEL / 8;
    pa.in[2] = value; pa.out[2] = rv;  pa.n8[2] = MROWS * DMODEL / 8;
    pa.in[3] = Wq;    pa.out[3] = rwq; pa.n8[3] = DMODEL * DMODEL / 8;
    pa.in[4] = Wk;    pa.out[4] = rwk; pa.n8[4] = DMODEL * DMODEL / 8;
    pa.in[5] = Wv;    pa.out[5] = rwv; pa.n8[5] = DMODEL * DMODEL / 8;
    pa.in[6] = Wo;    pa.out[6] = rwo; pa.n8[6] = DMODEL * DMODEL / 8;
    dim3 pgrid((MROWS * DMODEL / 8 + 255) / 256, 7);
    permute_round<<<pgrid, 256>>>(pa);

    // fused QKV projections (grid.z selects matrix)
    GArgs qkv;
    qkv.X[0] = rq; qkv.W[0] = rwq; qkv.bias[0] = bq; qkv.Y[0] = qptr; qkv.mode[0] = 4;
    qkv.X[1] = rk; qkv.W[1] = rwk; qkv.bias[1] = bk; qkv.Y[1] = kptr; qkv.mode[1] = 3;
    qkv.X[2] = rv; qkv.W[2] = rwv; qkv.bias[2] = bv; qkv.Y[2] = vptr; qkv.mode[2] = 2;
    dim3 qkvgrid(DMODEL / 128, MROWS / 128, 3);   // (8, 32, 3)
    gemm_tf32<<<qkvgrid, 128, gemm_smem>>>(qkv);

    dim3 agrid(SEQ / 128, NHEADS, BATCH);         // (16, 16, 2)
    attn_kernel<<<agrid, 256, attn_smem>>>(qptr, kptr, vptr, aoptr);

    GArgs og;
    og.X[0] = aoptr; og.W[0] = rwo; og.bias[0] = bo; og.Y[0] = (float*)d_out; og.mode[0] = 0;
    og.X[1] = aoptr; og.W[1] = rwo; og.bias[1] = bo; og.Y[1] = (float*)d_out; og.mode[1] = 0;
    og.X[2] = aoptr; og.W[2] = rwo; og.bias[2] = bo; og.Y[2] = (float*)d_out; og.mode[2] = 0;
    dim3 ogrid(DMODEL / 128, MROWS / 128, 1);     // (8, 32, 1)
    gemm_tf32<<<ogrid, 128, gemm_smem>>>(og);
}